// round 1
// baseline (speedup 1.0000x reference)
#include <cuda_runtime.h>

#define U_MAX 128
#define TPB   256
#define MAX_BLOCKS 4096

// Scratch (no device allocation allowed -> __device__ globals)
__device__ float g_w[U_MAX];            // aggregated inbound weights per source j
__device__ float g_part_final[MAX_BLOCKS];  // per-block partial sum of final
__device__ float g_part_in[MAX_BLOCKS];     // per-block partial sum of input_spikes

// ---------------------------------------------------------------------------
// Kernel 1: w[j] = 3 * sum_i (conn[i][j] > 0.1 ? conn[i][j] : 0)
// conn is [U,U] row-major; threads j read conn[i*U + j] -> coalesced across j.
// ---------------------------------------------------------------------------
__global__ void kw(const float* __restrict__ conn, int U) {
    int j = threadIdx.x;
    if (j >= U) return;
    float s = 0.0f;
#pragma unroll 8
    for (int i = 0; i < U; ++i) {
        float c = conn[i * U + j];
        s += (c > 0.1f) ? c : 0.0f;
    }
    g_w[j] = 3.0f * s;
}

// ---------------------------------------------------------------------------
// Kernel 2 (the 128 MB streamer):
//   final[tn] = 0.5 * sum_j w[j]*unit[j][tn] + 1.5 * target[tn]
// One float4 column per thread; j-loop unrolled x8 for MLP. Also produces
// deterministic per-block partial sums of final and input_spikes.
// ---------------------------------------------------------------------------
__global__ void __launch_bounds__(TPB)
kmain(const float4* __restrict__ unit,
      const float4* __restrict__ tgt,
      const float4* __restrict__ inspk,
      float4* __restrict__ out,
      int U, int TN4) {
    __shared__ float ws[U_MAX];
    __shared__ float redf[TPB / 32];
    __shared__ float redi[TPB / 32];

    int t = threadIdx.x;
    if (t < U) ws[t] = g_w[t];
    __syncthreads();

    int idx = blockIdx.x * TPB + t;            // one float4 column per thread
    const float4* p = unit + idx;

    float4 acc = make_float4(0.f, 0.f, 0.f, 0.f);
#pragma unroll 8
    for (int j = 0; j < U; ++j) {
        float4 v = p[(long)j * TN4];
        float w = ws[j];
        acc.x = fmaf(w, v.x, acc.x);
        acc.y = fmaf(w, v.y, acc.y);
        acc.z = fmaf(w, v.z, acc.z);
        acc.w = fmaf(w, v.w, acc.w);
    }

    float4 tg = tgt[idx];
    float4 f;
    f.x = fmaf(tg.x, 1.5f, acc.x * 0.5f);
    f.y = fmaf(tg.y, 1.5f, acc.y * 0.5f);
    f.z = fmaf(tg.z, 1.5f, acc.z * 0.5f);
    f.w = fmaf(tg.w, 1.5f, acc.w * 0.5f);
    out[idx] = f;

    float lf = f.x + f.y + f.z + f.w;
    float4 is4 = inspk[idx];
    float li = is4.x + is4.y + is4.z + is4.w;

    // deterministic warp tree reduce
#pragma unroll
    for (int o = 16; o > 0; o >>= 1) {
        lf += __shfl_down_sync(0xFFFFFFFFu, lf, o);
        li += __shfl_down_sync(0xFFFFFFFFu, li, o);
    }
    if ((t & 31) == 0) { redf[t >> 5] = lf; redi[t >> 5] = li; }
    __syncthreads();
    if (t == 0) {
        float a = 0.f, b = 0.f;
#pragma unroll
        for (int k = 0; k < TPB / 32; ++k) { a += redf[k]; b += redi[k]; }
        g_part_final[blockIdx.x] = a;
        g_part_in[blockIdx.x]    = b;
    }
}

// ---------------------------------------------------------------------------
// Kernel 3: every block deterministically reduces the partials (tiny, L2),
// computes the boost scalar, and conditionally applies the boost.
// When mean >= 0.2 (the expected case for this data) no gmem traffic happens
// beyond the partial reads.
// ---------------------------------------------------------------------------
__global__ void __launch_bounds__(TPB)
kfin(const float4* __restrict__ rb,
     float4* __restrict__ out,
     int nblocks, int TN4) {
    __shared__ float sf[TPB];
    __shared__ float si[TPB];
    __shared__ float s_boost;

    int t = threadIdx.x;
    float a = 0.f, b = 0.f;
    for (int k = t; k < nblocks; k += TPB) { a += g_part_final[k]; b += g_part_in[k]; }
    sf[t] = a; si[t] = b;
    __syncthreads();
#pragma unroll
    for (int s = TPB / 2; s > 0; s >>= 1) {
        if (t < s) { sf[t] += sf[t + s]; si[t] += si[t + s]; }
        __syncthreads();
    }
    if (t == 0) {
        float TNf = (float)TN4 * 4.0f;
        float mean = sf[0] / TNf;
        float input_rate = (si[0] / TNf) * 1000.0f;
        float target_mean = (input_rate + 20.0f) * 0.01f;
        float boost = fmaxf(0.0f, target_mean - mean);
        s_boost = (mean < 0.2f) ? (boost * 2.0f) : 0.0f;
    }
    __syncthreads();

    float bs = s_boost;
    if (bs != 0.0f) {
        int idx = blockIdx.x * TPB + t;
        float4 r = rb[idx];
        float4 o = out[idx];
        o.x = fmaf(r.x, bs, o.x);
        o.y = fmaf(r.y, bs, o.y);
        o.z = fmaf(r.z, bs, o.z);
        o.w = fmaf(r.w, bs, o.w);
        out[idx] = o;
    }
}

// ---------------------------------------------------------------------------
// Launch
// Inputs (metadata order): input_spikes [T,N], unit_outputs [U,T,N],
// conn [U,U], target_spikes [T,N], rand_bias [T,N]. Output: [T,N] float32.
// ---------------------------------------------------------------------------
extern "C" void kernel_launch(void* const* d_in, const int* in_sizes, int n_in,
                              void* d_out, int out_size) {
    const float* inspk = (const float*)d_in[0];
    const float* unit  = (const float*)d_in[1];
    const float* conn  = (const float*)d_in[2];
    const float* tgt   = (const float*)d_in[3];
    const float* rb    = (const float*)d_in[4];
    float* out = (float*)d_out;

    int TN  = in_sizes[0];               // 262144
    int U   = in_sizes[1] / TN;          // 128
    int TN4 = TN / 4;                    // 65536
    int mb  = TN4 / TPB;                 // 256 blocks

    kw<<<1, U_MAX>>>(conn, U);
    kmain<<<mb, TPB>>>((const float4*)unit, (const float4*)tgt,
                       (const float4*)inspk, (float4*)out, U, TN4);
    kfin<<<mb, TPB>>>((const float4*)rb, (float4*)out, mb, TN4);
}

// round 2
// speedup vs baseline: 1.3602x; 1.3602x over previous
#include <cuda_runtime.h>

#define U_MAX 128
#define TPB   256
#define MAX_BLOCKS 4096

// Scratch (no device allocation allowed -> __device__ globals)
__device__ float g_part_final[MAX_BLOCKS];  // per-block partial sum of final
__device__ float g_part_in[MAX_BLOCKS];     // per-block partial sum of input_spikes

// ---------------------------------------------------------------------------
// Kernel 1 (the 128 MB streamer), with fused weight computation:
//   prologue (per block, conn hits L2 after first block):
//     w[j] = 3 * sum_i (conn[i][j] > 0.1 ? conn[i][j] : 0)
//   main:
//     final[tn] = 0.5 * sum_j w[j]*unit[j][tn] + 1.5 * target[tn]
// One float4 column per thread; j-loop unrolled x16 for MLP. Also produces
// deterministic per-block partial sums of final and input_spikes.
// ---------------------------------------------------------------------------
__global__ void __launch_bounds__(TPB)
kmain(const float4* __restrict__ conn4,   // conn as float4*, row stride 32
      const float4* __restrict__ unit,
      const float4* __restrict__ tgt,
      const float4* __restrict__ inspk,
      float4* __restrict__ out,
      int TN4) {
    __shared__ float4 part[8][32];        // row-partition partials
    __shared__ float  ws[U_MAX];
    __shared__ float  redf[TPB / 32];
    __shared__ float  redi[TPB / 32];

    const int t  = threadIdx.x;
    const int jc = t & 31;                // column group (4 cols)
    const int rp = t >> 5;                // row partition (16 rows each)

    // --- fused w computation: 16 independent L2/DRAM loads, full MLP ---
    {
        float4 acc = make_float4(0.f, 0.f, 0.f, 0.f);
#pragma unroll
        for (int r = 0; r < 16; ++r) {
            int row = rp * 16 + r;
            float4 c = conn4[row * 32 + jc];
            acc.x += (c.x > 0.1f) ? c.x : 0.0f;
            acc.y += (c.y > 0.1f) ? c.y : 0.0f;
            acc.z += (c.z > 0.1f) ? c.z : 0.0f;
            acc.w += (c.w > 0.1f) ? c.w : 0.0f;
        }
        part[rp][jc] = acc;
    }
    __syncthreads();
    if (t < 32) {
        float4 s = make_float4(0.f, 0.f, 0.f, 0.f);
#pragma unroll
        for (int r = 0; r < 8; ++r) {
            float4 p = part[r][t];
            s.x += p.x; s.y += p.y; s.z += p.z; s.w += p.w;
        }
        ws[t * 4 + 0] = 3.0f * s.x;
        ws[t * 4 + 1] = 3.0f * s.y;
        ws[t * 4 + 2] = 3.0f * s.z;
        ws[t * 4 + 3] = 3.0f * s.w;
    }
    __syncthreads();

    // --- 128 MB stream ---
    const int idx = blockIdx.x * TPB + t;        // one float4 column per thread
    const float4* p = unit + idx;

    float4 acc = make_float4(0.f, 0.f, 0.f, 0.f);
#pragma unroll 16
    for (int j = 0; j < U_MAX; ++j) {
        float4 v = p[(long)j * TN4];
        float w = ws[j];
        acc.x = fmaf(w, v.x, acc.x);
        acc.y = fmaf(w, v.y, acc.y);
        acc.z = fmaf(w, v.z, acc.z);
        acc.w = fmaf(w, v.w, acc.w);
    }

    float4 tg = tgt[idx];
    float4 f;
    f.x = fmaf(tg.x, 1.5f, acc.x * 0.5f);
    f.y = fmaf(tg.y, 1.5f, acc.y * 0.5f);
    f.z = fmaf(tg.z, 1.5f, acc.z * 0.5f);
    f.w = fmaf(tg.w, 1.5f, acc.w * 0.5f);
    out[idx] = f;

    float lf = f.x + f.y + f.z + f.w;
    float4 is4 = inspk[idx];
    float li = is4.x + is4.y + is4.z + is4.w;

    // deterministic warp tree reduce
#pragma unroll
    for (int o = 16; o > 0; o >>= 1) {
        lf += __shfl_down_sync(0xFFFFFFFFu, lf, o);
        li += __shfl_down_sync(0xFFFFFFFFu, li, o);
    }
    if ((t & 31) == 0) { redf[t >> 5] = lf; redi[t >> 5] = li; }
    __syncthreads();
    if (t == 0) {
        float a = 0.f, b = 0.f;
#pragma unroll
        for (int k = 0; k < TPB / 32; ++k) { a += redf[k]; b += redi[k]; }
        g_part_final[blockIdx.x] = a;
        g_part_in[blockIdx.x]    = b;
    }
}

// ---------------------------------------------------------------------------
// Kernel 2: every block deterministically reduces the partials (tiny, L2),
// computes the boost scalar, and conditionally applies the boost.
// When mean >= 0.2 (the expected case for this data) no gmem traffic happens
// beyond the partial reads.
// ---------------------------------------------------------------------------
__global__ void __launch_bounds__(TPB)
kfin(const float4* __restrict__ rb,
     float4* __restrict__ out,
     int nblocks, int TN4) {
    __shared__ float sf[TPB];
    __shared__ float si[TPB];
    __shared__ float s_boost;

    int t = threadIdx.x;
    float a = 0.f, b = 0.f;
    for (int k = t; k < nblocks; k += TPB) { a += g_part_final[k]; b += g_part_in[k]; }
    sf[t] = a; si[t] = b;
    __syncthreads();
#pragma unroll
    for (int s = TPB / 2; s > 0; s >>= 1) {
        if (t < s) { sf[t] += sf[t + s]; si[t] += si[t + s]; }
        __syncthreads();
    }
    if (t == 0) {
        float TNf = (float)TN4 * 4.0f;
        float mean = sf[0] / TNf;
        float input_rate = (si[0] / TNf) * 1000.0f;
        float target_mean = (input_rate + 20.0f) * 0.01f;
        float boost = fmaxf(0.0f, target_mean - mean);
        s_boost = (mean < 0.2f) ? (boost * 2.0f) : 0.0f;
    }
    __syncthreads();

    float bs = s_boost;
    if (bs != 0.0f) {
        int idx = blockIdx.x * TPB + t;
        float4 r = rb[idx];
        float4 o = out[idx];
        o.x = fmaf(r.x, bs, o.x);
        o.y = fmaf(r.y, bs, o.y);
        o.z = fmaf(r.z, bs, o.z);
        o.w = fmaf(r.w, bs, o.w);
        out[idx] = o;
    }
}

// ---------------------------------------------------------------------------
// Launch
// Inputs (metadata order): input_spikes [T,N], unit_outputs [U,T,N],
// conn [U,U], target_spikes [T,N], rand_bias [T,N]. Output: [T,N] float32.
// ---------------------------------------------------------------------------
extern "C" void kernel_launch(void* const* d_in, const int* in_sizes, int n_in,
                              void* d_out, int out_size) {
    const float* inspk = (const float*)d_in[0];
    const float* unit  = (const float*)d_in[1];
    const float* conn  = (const float*)d_in[2];
    const float* tgt   = (const float*)d_in[3];
    const float* rb    = (const float*)d_in[4];
    float* out = (float*)d_out;

    int TN  = in_sizes[0];               // 262144
    int TN4 = TN / 4;                    // 65536
    int mb  = TN4 / TPB;                 // 256 blocks

    kmain<<<mb, TPB>>>((const float4*)conn, (const float4*)unit,
                       (const float4*)tgt, (const float4*)inspk,
                       (float4*)out, TN4);
    kfin<<<mb, TPB>>>((const float4*)rb, (float4*)out, mb, TN4);
}